// round 9
// baseline (speedup 1.0000x reference)
#include <cuda_runtime.h>
#include <cstdint>

// Correlation D=4, S1=S2=1 ; x1,x2:(4,128,256,256) f32 ; out:(4,81,256,256) f32
//
// PPT=8 scalar-FFMA kernel: tile 4x64 pixels, block 288 (9 warps = 9 ky),
// 2 CTAs/SM (18 warps), persistent grid 296 over 1024 tiles (each SM: 7 or 6).
// B-operand reuse: contiguous 8-pixel window -> 16 B-floats per 72 FMAs,
// cutting smem reads 1.78 -> 1.33 B/FMA so the smem port is no longer
// co-saturated with the FFMA pipe.
// Bank-conflict-free via custom lane map: lane = wg_lo | ty<<2 | wg_hi<<4
// (LDS.128 phases = 4wg x 2ty) with row strides S1F=68 (=4 mod 32) and
// S2F=76 (=12 mod 32): phase banks = {0,4,...,28}, a complete partition.
// cp.async 3-buffer ring, CB=4 channels/stage, 1 syncthreads/stage.

#define Himg 256
#define Wimg 256
#define Cimg 128
#define TH 4
#define TW 64
#define CB 4
#define NSTAGE 32
#define S1F 68                 // x1 smem row stride (floats)
#define S2F 76                 // x2 smem row stride (floats)
#define X1F (CB*TH*S1F)        // 1088 floats
#define X2F (CB*12*S2F)        // 3648 floats
#define BUFF (X1F + X2F)       // 4736 floats
#define BUFB (BUFF*4)          // 18944 B
#define SMEM_BYTES (3*BUFB)    // 56832 B per CTA
#define CSTRIDE (CB*Himg*Wimg) // gmem float advance per stage
#define NTHREADS 288
#define NTASKS 1120            // (64 x1 + 216 x2) chunks/channel * CB
#define NTILES 1024
#define NCTA 296

__device__ __forceinline__ void cp_async16(uint32_t dst, const float* src, int sz) {
    asm volatile("cp.async.cg.shared.global [%0], [%1], 16, %2;\n"
                 :: "r"(dst), "l"(src), "r"(sz) : "memory");
}
__device__ __forceinline__ void cp_commit() {
    asm volatile("cp.async.commit_group;\n" ::: "memory");
}

__global__ void __launch_bounds__(NTHREADS, 2)
corr_kernel(const float* __restrict__ x1, const float* __restrict__ x2,
            float* __restrict__ out) {
    const int tid  = threadIdx.x;
    const int lane = tid & 31;
    const int ky   = tid >> 5;                              // 0..8, one per warp
    const int wg   = (lane & 3) | (((lane >> 4) & 1) << 2); // 0..7 (8-px group)
    const int ty   = (lane >> 2) & 3;                       // 0..3 (row in tile)

    extern __shared__ float sm[];
    const uint32_t smem_u = (uint32_t)__cvta_generic_to_shared(sm);

    // compute-side base offsets (floats, tile-invariant)
    const float* x1rb = sm + ty * S1F + wg * 8;
    const float* x2rb = sm + X1F + (ty + ky) * S2F + wg * 8;

    float acc[72];
    #pragma unroll
    for (int i = 0; i < 72; ++i) acc[i] = 0.0f;

    // loader smem destinations: depend only on tid -> computed once
    uint32_t ldst[4];
    {
        #pragma unroll
        for (int k = 0; k < 4; ++k) {
            const int t = tid + k * NTHREADS;
            if (t < NTASKS) {
                const int c = t / 280;
                const int r = t % 280;
                if (r < 64) {
                    const int row = r >> 4, ch = r & 15;
                    ldst[k] = smem_u + (((c * TH + row) * S1F + ch * 4) << 2);
                } else {
                    const int r2 = r - 64;
                    const int row = r2 / 18, ch = r2 % 18;
                    ldst[k] = smem_u + ((X1F + (c * 12 + row) * S2F + ch * 4) << 2);
                }
            } else ldst[k] = smem_u;
        }
    }
    const bool has4 = (tid < (NTASKS - 3 * NTHREADS));   // tid < 256

    #pragma unroll 1
    for (int tile = blockIdx.x; tile < NTILES; tile += NCTA) {
        const int w0 = (tile & 3) * TW;
        const int h0 = ((tile >> 2) & 63) * TH;
        const int n  = tile >> 8;
        const float* x1n = x1 + (size_t)n * Cimg * Himg * Wimg;
        const float* x2n = x2 + (size_t)n * Cimg * Himg * Wimg;

        // ---- per-tile loader sources (gmem side of the fixed slots) ----
        const float* lsrc[4];
        int lsz[4];
        #pragma unroll
        for (int k = 0; k < 4; ++k) {
            const int t = tid + k * NTHREADS;
            if (t < NTASKS) {
                const int c = t / 280;
                const int r = t % 280;
                if (r < 64) {
                    const int row = r >> 4, ch = r & 15;
                    lsrc[k] = x1n + (size_t)(c * Himg + h0 + row) * Wimg + w0 + ch * 4;
                    lsz[k]  = 16;
                } else {
                    const int r2 = r - 64;
                    const int row = r2 / 18, ch = r2 % 18;
                    const int h  = h0 - 4 + row;
                    const int gw = w0 - 4 + ch * 4;
                    const bool ok = ((unsigned)h < (unsigned)Himg) &&
                                    (gw >= 0) && (gw <= Wimg - 4);
                    lsrc[k] = x2n + (size_t)(c * Himg + (ok ? h : 0)) * Wimg + (ok ? gw : 0);
                    lsz[k]  = ok ? 16 : 0;
                }
            } else { lsrc[k] = x1n; lsz[k] = 0; }
        }

        auto load_stage = [&](int buf) {
            const uint32_t base = buf * BUFB;
            cp_async16(ldst[0] + base, lsrc[0], lsz[0]);
            cp_async16(ldst[1] + base, lsrc[1], lsz[1]);
            cp_async16(ldst[2] + base, lsrc[2], lsz[2]);
            if (has4) cp_async16(ldst[3] + base, lsrc[3], lsz[3]);
            cp_commit();
            lsrc[0] += CSTRIDE; lsrc[1] += CSTRIDE;
            lsrc[2] += CSTRIDE; lsrc[3] += CSTRIDE;
        };

        // ---- pipeline: 3-buffer ring, 2-stage prologue ----
        load_stage(0);
        load_stage(1);

        int bufl = 2;
        int bufc = 0;
        #pragma unroll 1
        for (int s = 0; s < NSTAGE; ++s) {
            if (s < NSTAGE - 1) asm volatile("cp.async.wait_group 1;\n" ::: "memory");
            else                asm volatile("cp.async.wait_group 0;\n" ::: "memory");
            __syncthreads();
            if (s < NSTAGE - 2) {
                load_stage(bufl);
                bufl = (bufl == 2) ? 0 : bufl + 1;
            }
            // ---- compute stage bufc: CB=4 channels, 72 FMAs each ----
            {
                const float* x1b = x1rb + bufc * BUFF;
                const float* x2b = x2rb + bufc * BUFF;
                #pragma unroll
                for (int c = 0; c < CB; ++c) {
                    float4 a0 = *reinterpret_cast<const float4*>(x1b + c * (TH * S1F));
                    float4 a1 = *reinterpret_cast<const float4*>(x1b + c * (TH * S1F) + 4);
                    float4 b0 = *reinterpret_cast<const float4*>(x2b + c * (12 * S2F));
                    float4 b1 = *reinterpret_cast<const float4*>(x2b + c * (12 * S2F) + 4);
                    float4 b2 = *reinterpret_cast<const float4*>(x2b + c * (12 * S2F) + 8);
                    float4 b3 = *reinterpret_cast<const float4*>(x2b + c * (12 * S2F) + 12);
                    const float av[8] = {a0.x, a0.y, a0.z, a0.w, a1.x, a1.y, a1.z, a1.w};
                    const float v[16] = {b0.x, b0.y, b0.z, b0.w, b1.x, b1.y, b1.z, b1.w,
                                         b2.x, b2.y, b2.z, b2.w, b3.x, b3.y, b3.z, b3.w};
                    #pragma unroll
                    for (int p = 0; p < 8; ++p)
                        #pragma unroll
                        for (int kx = 0; kx < 9; ++kx)
                            acc[p * 9 + kx] = fmaf(av[p], v[p + kx], acc[p * 9 + kx]);
                }
            }
            bufc = (bufc == 2) ? 0 : bufc + 1;
        }

        // ---- epilogue ----
        const float inv = 1.0f / (float)Cimg;
        float* op = out + ((size_t)(n * 81 + ky * 9) * (Himg * Wimg))
                        + (size_t)(h0 + ty) * Wimg + w0 + wg * 8;
        #pragma unroll
        for (int kx = 0; kx < 9; ++kx) {
            float4 r0, r1;
            r0.x = acc[0 * 9 + kx] * inv;  r0.y = acc[1 * 9 + kx] * inv;
            r0.z = acc[2 * 9 + kx] * inv;  r0.w = acc[3 * 9 + kx] * inv;
            r1.x = acc[4 * 9 + kx] * inv;  r1.y = acc[5 * 9 + kx] * inv;
            r1.z = acc[6 * 9 + kx] * inv;  r1.w = acc[7 * 9 + kx] * inv;
            *reinterpret_cast<float4*>(op + (size_t)kx * (Himg * Wimg))     = r0;
            *reinterpret_cast<float4*>(op + (size_t)kx * (Himg * Wimg) + 4) = r1;
        }
        #pragma unroll
        for (int i = 0; i < 72; ++i) acc[i] = 0.0f;
    }
}

extern "C" void kernel_launch(void* const* d_in, const int* in_sizes, int n_in,
                              void* d_out, int out_size) {
    const float* x1 = (const float*)d_in[0];
    const float* x2 = (const float*)d_in[1];
    float* out = (float*)d_out;

    cudaFuncSetAttribute(corr_kernel, cudaFuncAttributeMaxDynamicSharedMemorySize,
                         SMEM_BYTES);

    dim3 block(NTHREADS, 1, 1);   // 288 threads = 9 warps (one ky per warp)
    dim3 grid(NCTA, 1, 1);        // persistent: 2 CTAs per SM
    corr_kernel<<<grid, block, SMEM_BYTES>>>(x1, x2, out);
}

// round 11
// speedup vs baseline: 1.1288x; 1.1288x over previous
#include <cuda_runtime.h>
#include <cstdint>

// Correlation D=4, S1=S2=1 ; x1,x2:(4,128,256,256) f32 ; out:(4,81,256,256) f32
//
// R8 champion compute (block (8,8,9)=576 thr, tile 8x32, PPT=4 scalar FFMA,
// 36 acc/thread, CB=8, persistent grid=148) with a WIDER PIPELINE:
// 6-buffer cp.async ring, ONE barrier per TWO stages (wait_group 2).
// Loads run 4 stages ahead; WAR distance 6 (barrier at period p covers
// compute of period p-1 which used the buffer being overwritten).
// FIX vs R10: tile repoint moved to p==6 (stages 14,15 of the current tile
// are fetched at p==5; the next tile's stages 0..3 at p==6,7).

#define Himg 256
#define Wimg 256
#define Cimg 128
#define TH 8
#define TW 32
#define CB 8
#define NSTAGE 16
#define S2F 48
#define X1F (CB*TH*TW)        // 2048 floats (x1 part per buffer)
#define X2F (CB*16*S2F)       // 6144 floats (x2 part per buffer)
#define BUFF (X1F + X2F)      // 8192 floats
#define BUFB (BUFF*4)         // 32768 B
#define NBUF 6
#define SMEM_BYTES (NBUF*BUFB)   // 196608 B
#define CSTRIDE (CB*Himg*Wimg)
#define NTHREADS 576
#define NTASKS 1792
#define NTILES 1024
#define GRIDX 148

__device__ __forceinline__ void cp_async16(uint32_t dst, const float* src, int sz) {
    asm volatile("cp.async.cg.shared.global [%0], [%1], 16, %2;\n"
                 :: "r"(dst), "l"(src), "r"(sz) : "memory");
}
__device__ __forceinline__ void cp_commit() {
    asm volatile("cp.async.commit_group;\n" ::: "memory");
}

__global__ void __launch_bounds__(NTHREADS, 1)
corr_kernel(const float* __restrict__ x1, const float* __restrict__ x2,
            float* __restrict__ out) {
    const int wg = threadIdx.x;   // 0..7
    const int ty = threadIdx.y;   // 0..7
    const int ky = threadIdx.z;   // 0..8
    const int tid = wg + (ty << 3) + (ky << 6);

    extern __shared__ float sm[];
    const uint32_t smem_u = (uint32_t)__cvta_generic_to_shared(sm);

    // ---------- loader slot state (re-pointed once per tile) ----------
    const float* lsrc[4] = {x1, x1, x1, x1};
    uint32_t     ldst[4] = {smem_u, smem_u, smem_u, smem_u};
    int          lsz[4]  = {0, 0, 0, 0};
    const bool has4 = (tid < (NTASKS - 3 * NTHREADS));   // tid < 64

    auto make_slots = [&](int t_idx) {
        const int w0 = (t_idx & 7) * TW;
        const int h0 = ((t_idx >> 3) & 31) * TH;
        const int n  = t_idx >> 8;
        const float* x1n = x1 + (size_t)n * Cimg * Himg * Wimg;
        const float* x2n = x2 + (size_t)n * Cimg * Himg * Wimg;
        #pragma unroll
        for (int k = 0; k < 4; ++k) {
            const int t = tid + k * NTHREADS;
            if (t < NTASKS) {
                const int c = t / 224;
                const int r = t % 224;
                if (r < 64) {
                    const int row = r >> 3, v = r & 7;
                    lsrc[k] = x1n + ((size_t)(c * Himg + h0 + row)) * Wimg + w0 + v * 4;
                    ldst[k] = smem_u + ((c * TH + row) * TW + v * 4) * 4;
                    lsz[k]  = 16;
                } else {
                    const int r2 = r - 64;
                    const int row = r2 / 10, v = r2 % 10;
                    const int hr = h0 - 4 + row;
                    const int gw = w0 - 4 + v * 4;
                    const bool ok = ((unsigned)hr < (unsigned)Himg) && (gw >= 0) && (gw <= Wimg - 4);
                    lsrc[k] = x2n + ((size_t)(c * Himg + (ok ? hr : 0))) * Wimg + (ok ? gw : 0);
                    ldst[k] = smem_u + (X1F + (c * 16 + row) * S2F + v * 4) * 4;
                    lsz[k]  = ok ? 16 : 0;
                }
            }
        }
    };

    auto load_stage = [&](int buf) {
        const uint32_t base = buf * BUFB;
        cp_async16(ldst[0] + base, lsrc[0], lsz[0]);
        cp_async16(ldst[1] + base, lsrc[1], lsz[1]);
        cp_async16(ldst[2] + base, lsrc[2], lsz[2]);
        if (has4) cp_async16(ldst[3] + base, lsrc[3], lsz[3]);
        cp_commit();
        lsrc[0] += CSTRIDE; lsrc[1] += CSTRIDE; lsrc[2] += CSTRIDE; lsrc[3] += CSTRIDE;
    };

    // ---------- compute bases (tile-independent smem addresses) ----------
    const float* x1rb = sm + ty * TW + wg * 4;
    const float* x2rb = sm + X1F + (ty + ky) * S2F + wg * 4;

    float acc[36];
    #pragma unroll
    for (int i = 0; i < 36; ++i) acc[i] = 0.0f;

    auto compute_stage = [&](int buf) {
        const float* x1b = x1rb + buf * BUFF;
        const float* x2b = x2rb + buf * BUFF;
        #pragma unroll
        for (int c = 0; c < CB; ++c) {
            float4 a  = *reinterpret_cast<const float4*>(x1b + c * (TH * TW));
            float4 b0 = *reinterpret_cast<const float4*>(x2b + c * (16 * S2F));
            float4 b1 = *reinterpret_cast<const float4*>(x2b + c * (16 * S2F) + 4);
            float4 b2 = *reinterpret_cast<const float4*>(x2b + c * (16 * S2F) + 8);
            const float av[4] = {a.x, a.y, a.z, a.w};
            const float v[12] = {b0.x, b0.y, b0.z, b0.w,
                                 b1.x, b1.y, b1.z, b1.w,
                                 b2.x, b2.y, b2.z, b2.w};
            #pragma unroll
            for (int p = 0; p < 4; ++p)
                #pragma unroll
                for (int kx = 0; kx < 9; ++kx)
                    acc[p * 9 + kx] = fmaf(av[p], v[p + kx], acc[p * 9 + kx]);
        }
    };

    // ---------- persistent tile loop, 6-buffer ring, barrier per 2 stages ----
    // Invariant at period p: pending groups = stages {2p..2p+3};
    // wait_group 2 -> stages 2p,2p+1 complete. Loads at period p fetch
    // stages 2p+4,2p+5. Stage indices run continuously across tiles:
    // periods 6,7 of a tile fetch the NEXT tile's stages 0..3, so the
    // repoint happens at the START of period 6 (after its barrier).
    make_slots(blockIdx.x);
    load_stage(0);   // stage 0
    load_stage(1);   // stage 1
    load_stage(2);   // stage 2
    load_stage(3);   // stage 3
    int bufl = 4;    // buffer for next load  (stage mod 6)
    int bufc = 0;    // buffer for next compute

    #pragma unroll 1
    for (int tile = blockIdx.x; tile < NTILES; tile += GRIDX) {
        #pragma unroll 1
        for (int p = 0; p < 8; ++p) {
            asm volatile("cp.async.wait_group 2;\n" ::: "memory");
            __syncthreads();
            if (p == 6) {   // periods 6,7 load the next tile's stages 0..3
                const int nxt = tile + GRIDX;
                make_slots(nxt < NTILES ? nxt : tile);
            }
            load_stage(bufl);  bufl = (bufl == NBUF - 1) ? 0 : bufl + 1;
            load_stage(bufl);  bufl = (bufl == NBUF - 1) ? 0 : bufl + 1;
            compute_stage(bufc); bufc = (bufc == NBUF - 1) ? 0 : bufc + 1;
            compute_stage(bufc); bufc = (bufc == NBUF - 1) ? 0 : bufc + 1;
        }

        // ---------- epilogue (overlaps next tile's in-flight loads) ----------
        const int w0 = (tile & 7) * TW;
        const int h0 = ((tile >> 3) & 31) * TH;
        const int n  = tile >> 8;
        const float inv = 1.0f / (float)Cimg;
        float* op = out + ((size_t)(n * 81 + ky * 9) * (Himg * Wimg))
                        + (size_t)(h0 + ty) * Wimg + w0 + wg * 4;
        #pragma unroll
        for (int kx = 0; kx < 9; ++kx) {
            float4 r;
            r.x = acc[0 * 9 + kx] * inv;
            r.y = acc[1 * 9 + kx] * inv;
            r.z = acc[2 * 9 + kx] * inv;
            r.w = acc[3 * 9 + kx] * inv;
            *reinterpret_cast<float4*>(op + (size_t)kx * (Himg * Wimg)) = r;
        }
        #pragma unroll
        for (int i = 0; i < 36; ++i) acc[i] = 0.0f;
    }

    asm volatile("cp.async.wait_group 0;\n" ::: "memory");  // drain tail groups
}

extern "C" void kernel_launch(void* const* d_in, const int* in_sizes, int n_in,
                              void* d_out, int out_size) {
    const float* x1 = (const float*)d_in[0];
    const float* x2 = (const float*)d_in[1];
    float* out = (float*)d_out;

    cudaFuncSetAttribute(corr_kernel, cudaFuncAttributeMaxDynamicSharedMemorySize,
                         SMEM_BYTES);

    dim3 block(8, 8, 9);        // 576 threads
    dim3 grid(GRIDX, 1, 1);     // persistent: one CTA per SM
    corr_kernel<<<grid, block, SMEM_BYTES>>>(x1, x2, out);
}

// round 12
// speedup vs baseline: 1.1539x; 1.0222x over previous
#include <cuda_runtime.h>
#include <cstdint>

// Correlation D=4, S1=S2=1 ; x1,x2:(4,128,256,256) f32 ; out:(4,81,256,256) f32
//
// R8-proven skeleton (block (8,8,9)=576 thr, tile 8x32, CB=8, 3-buffer
// cp.async ring, persistent grid=148, 1 barrier/stage) with the compute
// swapped to PACKED f32x2 FMAs (FFMA2):
//   acc2[pp][kx] = pair over pixel pair pp in {(0,1),(2,3)}; 18 ull accs.
//   a-pairs (a0,a1),(a2,a3) come free from LDS.64 (even-aligned pairs).
//   b-pairs: kx even -> natural E pairs; kx odd -> O pairs (2 MOVs each).
// Register budget ~88 (<<113 cap) so no R4-style spill storm.

#define Himg 256
#define Wimg 256
#define Cimg 128
#define TH 8
#define TW 32
#define CB 8
#define NSTAGE 16
#define S2F 48
#define X1F (CB*TH*TW)        // 2048 floats (x1 part per buffer)
#define X2F (CB*16*S2F)       // 6144 floats (x2 part per buffer)
#define BUFF (X1F + X2F)      // 8192 floats
#define BUFB (BUFF*4)         // 32768 B
#define SMEM_BYTES (3*BUFB)   // 98304 B
#define CSTRIDE (CB*Himg*Wimg)
#define NTHREADS 576
#define NTASKS 1792
#define NTILES 1024
#define GRIDX 148

typedef unsigned long long ull;

__device__ __forceinline__ void cp_async16(uint32_t dst, const float* src, int sz) {
    asm volatile("cp.async.cg.shared.global [%0], [%1], 16, %2;\n"
                 :: "r"(dst), "l"(src), "r"(sz) : "memory");
}
__device__ __forceinline__ void cp_commit() {
    asm volatile("cp.async.commit_group;\n" ::: "memory");
}
__device__ __forceinline__ ull ffma2(ull a, ull b, ull c) {
    ull d;
    asm("fma.rn.f32x2 %0, %1, %2, %3;" : "=l"(d) : "l"(a), "l"(b), "l"(c));
    return d;
}
// {lo = hi(e0), hi = lo(e1)} : the odd-offset pair (v[2j+1], v[2j+2])
__device__ __forceinline__ ull oddpair(ull e0, ull e1) {
    ull r;
    asm("mov.b64 %0, {%1, %2};" : "=l"(r)
        : "r"((unsigned)(e0 >> 32)), "r"((unsigned)e1));
    return r;
}
__device__ __forceinline__ float f2lo(ull a) { return __uint_as_float((unsigned)a); }
__device__ __forceinline__ float f2hi(ull a) { return __uint_as_float((unsigned)(a >> 32)); }

__global__ void __launch_bounds__(NTHREADS, 1)
corr_kernel(const float* __restrict__ x1, const float* __restrict__ x2,
            float* __restrict__ out) {
    const int wg = threadIdx.x;   // 0..7
    const int ty = threadIdx.y;   // 0..7
    const int ky = threadIdx.z;   // 0..8
    const int tid = wg + (ty << 3) + (ky << 6);

    extern __shared__ float sm[];
    const uint32_t smem_u = (uint32_t)__cvta_generic_to_shared(sm);

    // ---------- loader slot state (re-pointed once per tile) ----------
    const float* lsrc[4] = {x1, x1, x1, x1};
    uint32_t     ldst[4] = {smem_u, smem_u, smem_u, smem_u};
    int          lsz[4]  = {0, 0, 0, 0};
    const bool has4 = (tid < (NTASKS - 3 * NTHREADS));   // tid < 64

    auto make_slots = [&](int t_idx) {
        const int w0 = (t_idx & 7) * TW;
        const int h0 = ((t_idx >> 3) & 31) * TH;
        const int n  = t_idx >> 8;
        const float* x1n = x1 + (size_t)n * Cimg * Himg * Wimg;
        const float* x2n = x2 + (size_t)n * Cimg * Himg * Wimg;
        #pragma unroll
        for (int k = 0; k < 4; ++k) {
            const int t = tid + k * NTHREADS;
            if (t < NTASKS) {
                const int c = t / 224;
                const int r = t % 224;
                if (r < 64) {
                    const int row = r >> 3, v = r & 7;
                    lsrc[k] = x1n + ((size_t)(c * Himg + h0 + row)) * Wimg + w0 + v * 4;
                    ldst[k] = smem_u + ((c * TH + row) * TW + v * 4) * 4;
                    lsz[k]  = 16;
                } else {
                    const int r2 = r - 64;
                    const int row = r2 / 10, v = r2 % 10;
                    const int hr = h0 - 4 + row;
                    const int gw = w0 - 4 + v * 4;
                    const bool ok = ((unsigned)hr < (unsigned)Himg) && (gw >= 0) && (gw <= Wimg - 4);
                    lsrc[k] = x2n + ((size_t)(c * Himg + (ok ? hr : 0))) * Wimg + (ok ? gw : 0);
                    ldst[k] = smem_u + (X1F + (c * 16 + row) * S2F + v * 4) * 4;
                    lsz[k]  = ok ? 16 : 0;
                }
            }
        }
    };

    auto load_stage = [&](int buf) {
        const uint32_t base = buf * BUFB;
        cp_async16(ldst[0] + base, lsrc[0], lsz[0]);
        cp_async16(ldst[1] + base, lsrc[1], lsz[1]);
        cp_async16(ldst[2] + base, lsrc[2], lsz[2]);
        if (has4) cp_async16(ldst[3] + base, lsrc[3], lsz[3]);
        cp_commit();
        lsrc[0] += CSTRIDE; lsrc[1] += CSTRIDE; lsrc[2] += CSTRIDE; lsrc[3] += CSTRIDE;
    };

    // ---------- compute bases (tile-independent smem addresses) ----------
    // all offsets are even floats -> 8B-aligned -> valid ull (LDS.64) loads
    const float* x1rb = sm + ty * TW + wg * 4;
    const float* x2rb = sm + X1F + (ty + ky) * S2F + wg * 4;

    // acc2[0][kx] = (out[px0][kx], out[px1][kx]) ; acc2[1][kx] = (px2, px3)
    ull acc01[9], acc23[9];
    #pragma unroll
    for (int kx = 0; kx < 9; ++kx) { acc01[kx] = 0ull; acc23[kx] = 0ull; }

    auto compute_stage = [&](int buf) {
        const float* x1b = x1rb + buf * BUFF;
        const float* x2b = x2rb + buf * BUFF;
        #pragma unroll
        for (int c = 0; c < CB; ++c) {
            const ull* ap = reinterpret_cast<const ull*>(x1b + c * (TH * TW));
            const ull* vp = reinterpret_cast<const ull*>(x2b + c * (16 * S2F));
            const ull A01 = ap[0];            // (a0, a1)
            const ull A23 = ap[1];            // (a2, a3)
            const ull E0 = vp[0], E1 = vp[1], E2 = vp[2];
            const ull E3 = vp[3], E4 = vp[4], E5 = vp[5];
            const ull O0 = oddpair(E0, E1);   // (v1, v2)
            const ull O1 = oddpair(E1, E2);   // (v3, v4)
            const ull O2 = oddpair(E2, E3);   // (v5, v6)
            const ull O3 = oddpair(E3, E4);   // (v7, v8)
            const ull O4 = oddpair(E4, E5);   // (v9, v10)
            // px pair (0,1): b-pair for kx = (v[kx], v[kx+1])
            acc01[0] = ffma2(A01, E0, acc01[0]);
            acc01[1] = ffma2(A01, O0, acc01[1]);
            acc01[2] = ffma2(A01, E1, acc01[2]);
            acc01[3] = ffma2(A01, O1, acc01[3]);
            acc01[4] = ffma2(A01, E2, acc01[4]);
            acc01[5] = ffma2(A01, O2, acc01[5]);
            acc01[6] = ffma2(A01, E3, acc01[6]);
            acc01[7] = ffma2(A01, O3, acc01[7]);
            acc01[8] = ffma2(A01, E4, acc01[8]);
            // px pair (2,3): b-pair for kx = (v[kx+2], v[kx+3])
            acc23[0] = ffma2(A23, E1, acc23[0]);
            acc23[1] = ffma2(A23, O1, acc23[1]);
            acc23[2] = ffma2(A23, E2, acc23[2]);
            acc23[3] = ffma2(A23, O2, acc23[3]);
            acc23[4] = ffma2(A23, E3, acc23[4]);
            acc23[5] = ffma2(A23, O3, acc23[5]);
            acc23[6] = ffma2(A23, E4, acc23[6]);
            acc23[7] = ffma2(A23, O4, acc23[7]);
            acc23[8] = ffma2(A23, E5, acc23[8]);
        }
    };

    // ---------- persistent tile loop with seamless 3-buffer ring ----------
    make_slots(blockIdx.x);
    load_stage(0);       // tile0 stage 0
    load_stage(1);       // tile0 stage 1
    int bufl = 2;        // load target (stage s+2 of rolling counter)
    int bufc = 0;        // compute buffer

    #pragma unroll 1
    for (int tile = blockIdx.x; tile < NTILES; tile += GRIDX) {
        // stages 0..13: load this tile's stages 2..15
        #pragma unroll 1
        for (int s = 0; s < NSTAGE - 2; ++s) {
            asm volatile("cp.async.wait_group 1;\n" ::: "memory");
            __syncthreads();
            load_stage(bufl);
            bufl = (bufl == 2) ? 0 : bufl + 1;
            compute_stage(bufc);
            bufc = (bufc == 2) ? 0 : bufc + 1;
        }
        // re-point loader at next tile (clamped on the last tile)
        {
            int nxt = tile + GRIDX;
            make_slots(nxt < NTILES ? nxt : tile);
        }
        // stages 14,15: load next tile's stages 0,1
        #pragma unroll 1
        for (int s = 0; s < 2; ++s) {
            asm volatile("cp.async.wait_group 1;\n" ::: "memory");
            __syncthreads();
            load_stage(bufl);
            bufl = (bufl == 2) ? 0 : bufl + 1;
            compute_stage(bufc);
            bufc = (bufc == 2) ? 0 : bufc + 1;
        }

        // ---------- epilogue (overlaps next tile's in-flight loads) --------
        const int w0 = (tile & 7) * TW;
        const int h0 = ((tile >> 3) & 31) * TH;
        const int n  = tile >> 8;
        const float inv = 1.0f / (float)Cimg;
        float* op = out + ((size_t)(n * 81 + ky * 9) * (Himg * Wimg))
                        + (size_t)(h0 + ty) * Wimg + w0 + wg * 4;
        #pragma unroll
        for (int kx = 0; kx < 9; ++kx) {
            float4 r;
            r.x = f2lo(acc01[kx]) * inv;
            r.y = f2hi(acc01[kx]) * inv;
            r.z = f2lo(acc23[kx]) * inv;
            r.w = f2hi(acc23[kx]) * inv;
            *reinterpret_cast<float4*>(op + (size_t)kx * (Himg * Wimg)) = r;
            acc01[kx] = 0ull;
            acc23[kx] = 0ull;
        }
    }
}

extern "C" void kernel_launch(void* const* d_in, const int* in_sizes, int n_in,
                              void* d_out, int out_size) {
    const float* x1 = (const float*)d_in[0];
    const float* x2 = (const float*)d_in[1];
    float* out = (float*)d_out;

    cudaFuncSetAttribute(corr_kernel, cudaFuncAttributeMaxDynamicSharedMemorySize,
                         SMEM_BYTES);

    dim3 block(8, 8, 9);        // 576 threads
    dim3 grid(GRIDX, 1, 1);     // persistent: one CTA per SM
    corr_kernel<<<grid, block, SMEM_BYTES>>>(x1, x2, out);
}

// round 13
// speedup vs baseline: 1.1878x; 1.0294x over previous
#include <cuda_runtime.h>
#include <cstdint>

// Correlation D=4, S1=S2=1 ; x1,x2:(4,128,256,256) f32 ; out:(4,81,256,256) f32
//
// R8 champion compute with the block SPLIT into two independent CTAs per SM:
// block (8,4,9)=288 thr (tile 4x32, PPT=4 scalar FFMA, 36 acc), 2 CTAs/SM,
// persistent grid=296 over 2048 tiles (each CTA 7 or 6 tiles). Sibling CTAs
// have independent barriers/pipelines -> their LDS bursts interleave instead
// of synchronizing, feeding the FFMA pipe through each other's bubbles.
// 3-buffer cp.async ring, CB=8, 1 barrier/stage, seamless tile transitions.

#define Himg 256
#define Wimg 256
#define Cimg 128
#define TH 4
#define TW 32
#define CB 8
#define NSTAGE 16
#define S2F 48
#define X2R 12                 // x2 halo rows per channel (TH+8)
#define X1F (CB*TH*TW)         // 1024 floats (x1 part per buffer)
#define X2F (CB*X2R*S2F)       // 4608 floats (x2 part per buffer)
#define BUFF (X1F + X2F)       // 5632 floats
#define BUFB (BUFF*4)          // 22528 B
#define SMEM_BYTES (3*BUFB)    // 67584 B per CTA  (2 CTAs = 135KB < 228KB)
#define CSTRIDE (CB*Himg*Wimg)
#define NTHREADS 288
#define NTASKS 1216            // 8 ch * (32 x1 + 120 x2) float4 chunks
#define NTILES 2048            // 8 w * 64 h * 4 n
#define GRIDX 296

__device__ __forceinline__ void cp_async16(uint32_t dst, const float* src, int sz) {
    asm volatile("cp.async.cg.shared.global [%0], [%1], 16, %2;\n"
                 :: "r"(dst), "l"(src), "r"(sz) : "memory");
}
__device__ __forceinline__ void cp_commit() {
    asm volatile("cp.async.commit_group;\n" ::: "memory");
}

__global__ void __launch_bounds__(NTHREADS, 2)
corr_kernel(const float* __restrict__ x1, const float* __restrict__ x2,
            float* __restrict__ out) {
    const int wg = threadIdx.x;   // 0..7 : 4-pixel group
    const int ty = threadIdx.y;   // 0..3 : row in tile
    const int ky = threadIdx.z;   // 0..8 : displacement row (one per warp)
    const int tid = wg + (ty << 3) + (ky << 5);

    extern __shared__ float sm[];
    const uint32_t smem_u = (uint32_t)__cvta_generic_to_shared(sm);

    // ---------- loader slot state (re-pointed once per tile) ----------
    // task t < 1216: c = t/152, r = t%152
    //   r <  32 : x1 tile  row r/8 (0..3),   chunk r%8
    //   r >= 32 : x2 halo  row (r-32)/10 (0..11), chunk (r-32)%10 (zfill)
    const float* lsrc[5] = {x1, x1, x1, x1, x1};
    uint32_t     ldst[5] = {smem_u, smem_u, smem_u, smem_u, smem_u};
    int          lsz[5]  = {0, 0, 0, 0, 0};
    const bool has5 = (tid < (NTASKS - 4 * NTHREADS));   // tid < 64

    auto make_slots = [&](int t_idx) {
        const int w0 = (t_idx & 7) * TW;
        const int h0 = ((t_idx >> 3) & 63) * TH;
        const int n  = t_idx >> 9;
        const float* x1n = x1 + (size_t)n * Cimg * Himg * Wimg;
        const float* x2n = x2 + (size_t)n * Cimg * Himg * Wimg;
        #pragma unroll
        for (int k = 0; k < 5; ++k) {
            const int t = tid + k * NTHREADS;
            if (t < NTASKS) {
                const int c = t / 152;
                const int r = t % 152;
                if (r < 32) {
                    const int row = r >> 3, v = r & 7;
                    lsrc[k] = x1n + ((size_t)(c * Himg + h0 + row)) * Wimg + w0 + v * 4;
                    ldst[k] = smem_u + ((c * TH + row) * TW + v * 4) * 4;
                    lsz[k]  = 16;
                } else {
                    const int r2 = r - 32;
                    const int row = r2 / 10, v = r2 % 10;
                    const int hr = h0 - 4 + row;
                    const int gw = w0 - 4 + v * 4;
                    const bool ok = ((unsigned)hr < (unsigned)Himg) && (gw >= 0) && (gw <= Wimg - 4);
                    lsrc[k] = x2n + ((size_t)(c * Himg + (ok ? hr : 0))) * Wimg + (ok ? gw : 0);
                    ldst[k] = smem_u + (X1F + (c * X2R + row) * S2F + v * 4) * 4;
                    lsz[k]  = ok ? 16 : 0;
                }
            }
        }
    };

    auto load_stage = [&](int buf) {
        const uint32_t base = buf * BUFB;
        cp_async16(ldst[0] + base, lsrc[0], lsz[0]);
        cp_async16(ldst[1] + base, lsrc[1], lsz[1]);
        cp_async16(ldst[2] + base, lsrc[2], lsz[2]);
        cp_async16(ldst[3] + base, lsrc[3], lsz[3]);
        if (has5) cp_async16(ldst[4] + base, lsrc[4], lsz[4]);
        cp_commit();
        lsrc[0] += CSTRIDE; lsrc[1] += CSTRIDE; lsrc[2] += CSTRIDE;
        lsrc[3] += CSTRIDE; lsrc[4] += CSTRIDE;
    };

    // ---------- compute bases (tile-independent smem addresses) ----------
    const float* x1rb = sm + ty * TW + wg * 4;
    const float* x2rb = sm + X1F + (ty + ky) * S2F + wg * 4;   // ty+ky in 0..11

    float acc[36];
    #pragma unroll
    for (int i = 0; i < 36; ++i) acc[i] = 0.0f;

    auto compute_stage = [&](int buf) {
        const float* x1b = x1rb + buf * BUFF;
        const float* x2b = x2rb + buf * BUFF;
        #pragma unroll
        for (int c = 0; c < CB; ++c) {
            float4 a  = *reinterpret_cast<const float4*>(x1b + c * (TH * TW));
            float4 b0 = *reinterpret_cast<const float4*>(x2b + c * (X2R * S2F));
            float4 b1 = *reinterpret_cast<const float4*>(x2b + c * (X2R * S2F) + 4);
            float4 b2 = *reinterpret_cast<const float4*>(x2b + c * (X2R * S2F) + 8);
            const float av[4] = {a.x, a.y, a.z, a.w};
            const float v[12] = {b0.x, b0.y, b0.z, b0.w,
                                 b1.x, b1.y, b1.z, b1.w,
                                 b2.x, b2.y, b2.z, b2.w};
            #pragma unroll
            for (int p = 0; p < 4; ++p)
                #pragma unroll
                for (int kx = 0; kx < 9; ++kx)
                    acc[p * 9 + kx] = fmaf(av[p], v[p + kx], acc[p * 9 + kx]);
        }
    };

    // ---------- persistent tile loop with seamless 3-buffer ring ----------
    make_slots(blockIdx.x);
    load_stage(0);       // first tile stage 0
    load_stage(1);       // first tile stage 1
    int bufl = 2;        // load target (stage s+2 of rolling counter)
    int bufc = 0;        // compute buffer

    #pragma unroll 1
    for (int tile = blockIdx.x; tile < NTILES; tile += GRIDX) {
        // stages 0..13: load this tile's stages 2..15
        #pragma unroll 1
        for (int s = 0; s < NSTAGE - 2; ++s) {
            asm volatile("cp.async.wait_group 1;\n" ::: "memory");
            __syncthreads();
            load_stage(bufl);
            bufl = (bufl == 2) ? 0 : bufl + 1;
            compute_stage(bufc);
            bufc = (bufc == 2) ? 0 : bufc + 1;
        }
        // re-point loader at next tile (clamped on the last tile)
        {
            int nxt = tile + GRIDX;
            make_slots(nxt < NTILES ? nxt : tile);
        }
        // stages 14,15: load next tile's stages 0,1
        #pragma unroll 1
        for (int s = 0; s < 2; ++s) {
            asm volatile("cp.async.wait_group 1;\n" ::: "memory");
            __syncthreads();
            load_stage(bufl);
            bufl = (bufl == 2) ? 0 : bufl + 1;
            compute_stage(bufc);
            bufc = (bufc == 2) ? 0 : bufc + 1;
        }

        // ---------- epilogue (overlaps next tile's in-flight loads) --------
        const int w0 = (tile & 7) * TW;
        const int h0 = ((tile >> 3) & 63) * TH;
        const int n  = tile >> 9;
        const float inv = 1.0f / (float)Cimg;
        float* op = out + ((size_t)(n * 81 + ky * 9) * (Himg * Wimg))
                        + (size_t)(h0 + ty) * Wimg + w0 + wg * 4;
        #pragma unroll
        for (int kx = 0; kx < 9; ++kx) {
            float4 r;
            r.x = acc[0 * 9 + kx] * inv;
            r.y = acc[1 * 9 + kx] * inv;
            r.z = acc[2 * 9 + kx] * inv;
            r.w = acc[3 * 9 + kx] * inv;
            *reinterpret_cast<float4*>(op + (size_t)kx * (Himg * Wimg)) = r;
        }
        #pragma unroll
        for (int i = 0; i < 36; ++i) acc[i] = 0.0f;
    }
}

extern "C" void kernel_launch(void* const* d_in, const int* in_sizes, int n_in,
                              void* d_out, int out_size) {
    const float* x1 = (const float*)d_in[0];
    const float* x2 = (const float*)d_in[1];
    float* out = (float*)d_out;

    cudaFuncSetAttribute(corr_kernel, cudaFuncAttributeMaxDynamicSharedMemorySize,
                         SMEM_BYTES);

    dim3 block(8, 4, 9);        // 288 threads = 9 warps (one ky per warp)
    dim3 grid(GRIDX, 1, 1);     // persistent: 2 CTAs per SM
    corr_kernel<<<grid, block, SMEM_BYTES>>>(x1, x2, out);
}

// round 15
// speedup vs baseline: 1.2020x; 1.0120x over previous
#include <cuda_runtime.h>
#include <cstdint>

// Correlation D=4 via warp-level tensor cores: mma.sync m16n8k8 tf32 (base
// PTX feature -> legal on compute_103, unlike tcgen05 which needs _103a).
//
// CTA: 8 h-rows x 32 w = 256 px, 512 thr = 16 warps. Warp = m-tile of 16 px
// (2 h-rows x 8 w). Band GEMM: D[m=(il,wl)][n=(r,cc)] over K=128 channels,
// N = 10 x2-rows x 16 cc = 20 n-blocks of 8 (50.6% of MACs useful).
//   out[n,ky*9+kx,h0+2ip+il,w0+8wgp+wl] = D[il*8+wl][(il+ky)*2 blocks][wl+kx]/128
// Operands cvt.rna.tf32 at frag-load (REQUIRED: raw f32 would truncate=RZ,
// ~1e-2 bias -> fail; rna gives ~4e-4 unbiased -> pass).
// smem: x1 [c][8*32]+8pad (c-stride 264 = 8 mod 32), x2 [r][c][40]
// (k-stride 40 = 8 mod 32) -> all frag LDS bank-conflict-free.
// R8-proven 3-buffer cp.async ring, CB=8 ch/chunk, 16 chunks.

#define HW_ 65536
#define C_ 128
#define CB 8
#define NSTAGE 16
#define X1CH 2112                // x1 floats/chunk: 8 ch * 264
#define X2CH 5120                // x2 floats/chunk: 16 r * 8 ch * 40
#define BUFF (X1CH + X2CH)       // 7232 floats
#define BUFB (BUFF*4)            // 28928 B
#define SM_D (3*BUFB)            // 86784 B : epilogue D region
#define SMEM_BYTES (SM_D + 16*272*4)   // +17408 = 104192 B
#define CSTRIDE (CB*HW_)
#define NTHREADS 512
#define NTASKS 1792              // 1280 x2 + 512 x1 float4 tasks / chunk

__device__ __forceinline__ void cp_async16(uint32_t dst, const float* src, int sz) {
    asm volatile("cp.async.cg.shared.global [%0], [%1], 16, %2;\n"
                 :: "r"(dst), "l"(src), "r"(sz) : "memory");
}
__device__ __forceinline__ void cp_commit() {
    asm volatile("cp.async.commit_group;\n" ::: "memory");
}
__device__ __forceinline__ uint32_t tf32c(float x) {
    uint32_t r;
    asm("cvt.rna.tf32.f32 %0, %1;" : "=r"(r) : "f"(x));
    return r;
}

__global__ void __launch_bounds__(NTHREADS, 1)
corr_mma_kernel(const float* __restrict__ x1, const float* __restrict__ x2,
                float* __restrict__ out) {
    extern __shared__ float sm[];
    const uint32_t smem_u = (uint32_t)__cvta_generic_to_shared(sm);
    const int tid  = threadIdx.x;
    const int lane = tid & 31;
    const int wq   = tid >> 5;      // 0..15
    const int ip   = wq >> 2;       // i-pair: rows h0+2ip, h0+2ip+1
    const int wgp  = wq & 3;        // w-group: cols w0+8wgp..+7
    const int g    = lane >> 2;     // groupID
    const int kq   = lane & 3;      // threadID_in_group

    const int bx = blockIdx.x;
    const int w0 = (bx & 7) * 32;
    const int h0 = ((bx >> 3) & 31) * 8;
    const int n  = bx >> 8;
    const float* x1n = x1 + (size_t)n * C_ * HW_;
    const float* x2n = x2 + (size_t)n * C_ * HW_;

    // ---------- loader: fixed per-thread slots (computed once) ----------
    // t < 1280 : x2 halo  [rg 0..15][c 0..7][q 0..9]  (zfill at borders)
    // t >= 1280: x1 tile  [c 0..7][row 0..7][q 0..7]
    const float* lsrc[4];
    uint32_t     ldst[4];
    int          lsz[4];
    #pragma unroll
    for (int k = 0; k < 4; ++k) {
        const int t = tid + k * NTHREADS;
        if (t < NTASKS) {
            if (t < 1280) {
                const int rg = t / 80, rem = t % 80;
                const int c = rem / 10, q = rem % 10;
                const int h  = h0 - 4 + rg;
                const int gw = w0 - 4 + q * 4;
                const bool ok = ((unsigned)h < 256u) && (gw >= 0) && (gw <= 252);
                lsrc[k] = x2n + (size_t)c * HW_ + (ok ? ((size_t)h * 256 + gw) : 0);
                ldst[k] = smem_u + (uint32_t)(X1CH + (rg * 8 + c) * 40 + q * 4) * 4u;
                lsz[k]  = ok ? 16 : 0;
            } else {
                const int t2 = t - 1280;
                const int c = t2 / 64, rem = t2 % 64;
                const int row = rem / 8, q = rem % 8;
                lsrc[k] = x1n + (size_t)c * HW_ + (size_t)(h0 + row) * 256 + w0 + q * 4;
                ldst[k] = smem_u + (uint32_t)(c * 264 + row * 32 + q * 4) * 4u;
                lsz[k]  = 16;
            }
        } else { lsrc[k] = x1n; ldst[k] = smem_u; lsz[k] = 0; }
    }
    const bool has4 = (tid < (NTASKS - 3 * NTHREADS));   // tid < 256

    auto load_stage = [&](int buf) {
        const uint32_t base = buf * BUFB;
        cp_async16(ldst[0] + base, lsrc[0], lsz[0]);
        cp_async16(ldst[1] + base, lsrc[1], lsz[1]);
        cp_async16(ldst[2] + base, lsrc[2], lsz[2]);
        if (has4) cp_async16(ldst[3] + base, lsrc[3], lsz[3]);
        cp_commit();
        lsrc[0] += CSTRIDE; lsrc[1] += CSTRIDE; lsrc[2] += CSTRIDE; lsrc[3] += CSTRIDE;
    };

    // ---------- fragment offsets (floats, buffer-relative) ----------
    // A[m][k] : x1s[c=k][row=2ip+il][col=8wgp+wl], c-stride 264, row-stride 32
    const int a0off = kq * 264 + ip * 64 + wgp * 8 + g;
    // B[k][nc] for block (r,cb): x2s[rg=2ip+r][c=k][cc=8wgp+8cb+nc]
    const int bbase = X1CH + (ip * 16 + kq) * 40 + wgp * 8 + g;

    float acc[20][4];
    #pragma unroll
    for (int i = 0; i < 20; ++i)
        #pragma unroll
        for (int j = 0; j < 4; ++j) acc[i][j] = 0.0f;

    auto compute_stage = [&](int buf) {
        const float* bp = sm + buf * BUFF;
        const uint32_t A0 = tf32c(bp[a0off]);
        const uint32_t A1 = tf32c(bp[a0off + 32]);
        const uint32_t A2 = tf32c(bp[a0off + 1056]);
        const uint32_t A3 = tf32c(bp[a0off + 1088]);
        #pragma unroll
        for (int r = 0; r < 10; ++r) {
            #pragma unroll
            for (int cb = 0; cb < 2; ++cb) {
                const int o = bbase + r * 320 + cb * 8;
                const uint32_t B0 = tf32c(bp[o]);
                const uint32_t B1 = tf32c(bp[o + 160]);
                float* c = acc[r * 2 + cb];
                asm volatile(
                    "mma.sync.aligned.m16n8k8.row.col.f32.tf32.tf32.f32 "
                    "{%0,%1,%2,%3}, {%4,%5,%6,%7}, {%8,%9}, {%0,%1,%2,%3};"
                    : "+f"(c[0]), "+f"(c[1]), "+f"(c[2]), "+f"(c[3])
                    : "r"(A0), "r"(A1), "r"(A2), "r"(A3), "r"(B0), "r"(B1));
            }
        }
    };

    // ---------- 3-buffer ring (R8-proven accounting) ----------
    load_stage(0);
    load_stage(1);
    int bufl = 2, bufc = 0;
    #pragma unroll 1
    for (int s = 0; s < NSTAGE; ++s) {
        if (s < NSTAGE - 1) asm volatile("cp.async.wait_group 1;\n" ::: "memory");
        else                asm volatile("cp.async.wait_group 0;\n" ::: "memory");
        __syncthreads();
        if (s < NSTAGE - 2) {
            load_stage(bufl);
            bufl = (bufl == 2) ? 0 : bufl + 1;
        }
        compute_stage(bufc);
        bufc = (bufc == 2) ? 0 : bufc + 1;
    }

    // ---------- epilogue: per-warp D dump + band extraction ----------
    float* dbase = sm + (SM_D / 4) + wq * 272;    // [16][17] floats per warp
    const float inv = 1.0f / 128.0f;
    #pragma unroll 1
    for (int r = 0; r < 10; ++r) {
        #pragma unroll
        for (int cb = 0; cb < 2; ++cb) {
            const float* c = acc[r * 2 + cb];
            const int ccb = cb * 8 + 2 * kq;
            dbase[g * 17 + ccb]           = c[0];
            dbase[g * 17 + ccb + 1]       = c[1];
            dbase[(g + 8) * 17 + ccb]     = c[2];
            dbase[(g + 8) * 17 + ccb + 1] = c[3];
        }
        __syncwarp();
        #pragma unroll
        for (int il = 0; il < 2; ++il) {
            const int ky = r - il;
            if (ky >= 0 && ky < 9) {
                float* op = out + ((size_t)(n * 81 + ky * 9) * HW_)
                                + (size_t)(h0 + 2 * ip + il) * 256 + w0 + wgp * 8;
                #pragma unroll
                for (int t0 = 0; t0 < 3; ++t0) {
                    const int t = lane + t0 * 32;
                    if (t < 72) {
                        const int kx = t >> 3, wl = t & 7;
                        op[(size_t)kx * HW_ + wl] =
                            dbase[(il * 8 + wl) * 17 + wl + kx] * inv;
                    }
                }
            }
        }
        __syncwarp();
    }
}

extern "C" void kernel_launch(void* const* d_in, const int* in_sizes, int n_in,
                              void* d_out, int out_size) {
    const float* x1 = (const float*)d_in[0];
    const float* x2 = (const float*)d_in[1];
    float* out = (float*)d_out;

    cudaFuncSetAttribute(corr_mma_kernel, cudaFuncAttributeMaxDynamicSharedMemorySize,
                         SMEM_BYTES);

    dim3 block(NTHREADS, 1, 1);   // 512 threads = 16 warps
    dim3 grid(1024, 1, 1);        // 8 w-tiles x 32 h-tiles x 4 n
    corr_mma_kernel<<<grid, block, SMEM_BYTES>>>(x1, x2, out);
}